// round 9
// baseline (speedup 1.0000x reference)
#include <cuda_runtime.h>
#include <cuda_bf16.h>

// D_MODEL = 2048, QUAT_DIM = 512, B*T = 16384
// Inputs: x [B,T,2048] f32, q_left [4,512] f32, q_right [4,512] f32, gate [512] f32
// Output: [B,T,2048] f32
//
// gate broadcasts uniformly over the FFT axis => ifft(fft(x)*g).real == g*x.
// out[b,t,:,d] = ql_n[d] (X) ( x[b,t,:,d] (X) (g[d] * conj(qr_n[d])) )
// (gate folded into the right quaternion; both products applied per-lane).
//
// R8: float4 LDG.128/STG.128 (half the LSU ops, 2x bytes per outstanding load)
// + two-step Hamilton (32 regs of quats instead of 64 regs of fused matrix)
// + 2-deep software prefetch. 256 thr/block = two bt-rows in flight.

#define QD 512
#define NBT (4 * 4096)
#define ROWS 8              // bt-rows per block
#define NBLK (NBT / ROWS)   // 2048
#define THREADS 256
#define ITERS (ROWS / 2)    // 4 row-pairs; each half-block owns one row of the pair

__device__ __forceinline__ float4 f4_mul(float4 a, float4 b) {
    return make_float4(a.x * b.x, a.y * b.y, a.z * b.z, a.w * b.w);
}
__device__ __forceinline__ float4 f4_fma(float4 a, float4 b, float4 c) {
    return make_float4(fmaf(a.x, b.x, c.x), fmaf(a.y, b.y, c.y),
                       fmaf(a.z, b.z, c.z), fmaf(a.w, b.w, c.w));
}
__device__ __forceinline__ float4 f4_fms(float4 a, float4 b, float4 c) {
    // a*b - c  ... realized as fma(a,b,-c)
    return make_float4(fmaf(a.x, b.x, -c.x), fmaf(a.y, b.y, -c.y),
                       fmaf(a.z, b.z, -c.z), fmaf(a.w, b.w, -c.w));
}
__device__ __forceinline__ float4 f4_neg(float4 a) {
    return make_float4(-a.x, -a.y, -a.z, -a.w);
}

// Hamilton product h = a (X) b, elementwise over float4 feature lanes.
// a[0..3] = (w,x,y,z), b[0..3] = (w,x,y,z).
__device__ __forceinline__ void hamilton(const float4 a[4], const float4 b[4],
                                         float4 h[4]) {
    // w = aw*bw - ax*bx - ay*by - az*bz
    h[0] = f4_mul(a[0], b[0]);
    h[0] = f4_fms(f4_neg(a[1]), b[1], f4_neg(h[0]));  // h0 - ax*bx
    h[0] = f4_fma(f4_neg(a[2]), b[2], h[0]);
    h[0] = f4_fma(f4_neg(a[3]), b[3], h[0]);
    // x = aw*bx + ax*bw + ay*bz - az*by
    h[1] = f4_mul(a[0], b[1]);
    h[1] = f4_fma(a[1], b[0], h[1]);
    h[1] = f4_fma(a[2], b[3], h[1]);
    h[1] = f4_fma(f4_neg(a[3]), b[2], h[1]);
    // y = aw*by - ax*bz + ay*bw + az*bx
    h[2] = f4_mul(a[0], b[2]);
    h[2] = f4_fma(f4_neg(a[1]), b[3], h[2]);
    h[2] = f4_fma(a[2], b[0], h[2]);
    h[2] = f4_fma(a[3], b[1], h[2]);
    // z = aw*bz + ax*by - ay*bx + az*bw
    h[3] = f4_mul(a[0], b[3]);
    h[3] = f4_fma(a[1], b[2], h[3]);
    h[3] = f4_fma(f4_neg(a[2]), b[1], h[3]);
    h[3] = f4_fma(a[3], b[0], h[3]);
}

__global__ void __launch_bounds__(THREADS)
evolve_quat_kernel(const float* __restrict__ x,
                   const float* __restrict__ ql,
                   const float* __restrict__ qr,
                   const float* __restrict__ gate,
                   float* __restrict__ out) {
    const int lane = threadIdx.x & 127;     // feature-group thread
    const int half = threadIdx.x >> 7;      // which row of each pair
    const int d4 = lane * 4;
    const int row0 = blockIdx.x * ROWS + half;  // rows: row0, row0+2, +4, +6

    // ---- Load + normalize quaternions (float4 = 4 features per thread) ----
    float4 L[4], R[4];
#pragma unroll
    for (int i = 0; i < 4; i++) {
        L[i] = *reinterpret_cast<const float4*>(ql + i * QD + d4);
        R[i] = *reinterpret_cast<const float4*>(qr + i * QD + d4);
    }
    {
        float4 s = make_float4(1e-8f, 1e-8f, 1e-8f, 1e-8f);
#pragma unroll
        for (int i = 0; i < 4; i++) s = f4_fma(L[i], L[i], s);
        float4 inv = make_float4(rsqrtf(s.x), rsqrtf(s.y), rsqrtf(s.z), rsqrtf(s.w));
#pragma unroll
        for (int i = 0; i < 4; i++) L[i] = f4_mul(L[i], inv);
    }
    {
        float4 s = make_float4(1e-8f, 1e-8f, 1e-8f, 1e-8f);
#pragma unroll
        for (int i = 0; i < 4; i++) s = f4_fma(R[i], R[i], s);
        float4 inv = make_float4(rsqrtf(s.x), rsqrtf(s.y), rsqrtf(s.z), rsqrtf(s.w));
        // fold gate into the right quaternion, conjugate it (negate x,y,z)
        float4 g = *reinterpret_cast<const float4*>(gate + d4);
        float4 gi = f4_mul(g, inv);
        R[0] = f4_mul(R[0], gi);
        float4 ngi = f4_neg(gi);
#pragma unroll
        for (int i = 1; i < 4; i++) R[i] = f4_mul(R[i], ngi);
    }

    // ---- Stream 4 rows (stride 2) with 2-deep prefetch ----
    const float* xp = x + (size_t)row0 * 2048 + d4;
    float* op = out + (size_t)row0 * 2048 + d4;
    const size_t rstride = 2 * 2048;   // row-pair stride in floats

    float4 buf[2][4];
#pragma unroll
    for (int c = 0; c < 4; c++) {
        buf[0][c] = __ldcs(reinterpret_cast<const float4*>(xp + 0 * rstride + c * QD));
        buf[1][c] = __ldcs(reinterpret_cast<const float4*>(xp + 1 * rstride + c * QD));
    }

#pragma unroll
    for (int it = 0; it < ITERS; it++) {
        float4 in[4];
#pragma unroll
        for (int c = 0; c < 4; c++) in[c] = buf[it & 1][c];

        if (it + 2 < ITERS) {
#pragma unroll
            for (int c = 0; c < 4; c++)
                buf[it & 1][c] = __ldcs(reinterpret_cast<const float4*>(
                    xp + (size_t)(it + 2) * rstride + c * QD));
        }

        float4 t[4], o[4];
        hamilton(in, R, t);   // x (X) (g * conj(qr))
        hamilton(L, t, o);    // ql (X) ...

#pragma unroll
        for (int r = 0; r < 4; r++)
            __stcs(reinterpret_cast<float4*>(op + (size_t)it * rstride + r * QD), o[r]);
    }
}

extern "C" void kernel_launch(void* const* d_in, const int* in_sizes, int n_in,
                              void* d_out, int out_size) {
    const float* x    = (const float*)d_in[0];
    const float* ql   = (const float*)d_in[1];
    const float* qr   = (const float*)d_in[2];
    const float* gate = (const float*)d_in[3];
    float* out = (float*)d_out;

    evolve_quat_kernel<<<NBLK, THREADS>>>(x, ql, qr, gate, out);
}

// round 10
// speedup vs baseline: 1.1206x; 1.1206x over previous
#include <cuda_runtime.h>
#include <cuda_bf16.h>

// D_MODEL = 2048, QUAT_DIM = 512, B*T = 16384
// Inputs: x [B,T,2048] f32, q_left [4,512] f32, q_right [4,512] f32, gate [512] f32
// Output: [B,T,2048] f32
//
// gate broadcasts uniformly over the FFT axis => ifft(fft(x)*g).real == g*x.
// Both Hamilton products are linear in x => fused per-feature 4x4 matrix M[d].
//
// R9: persistent block-strided grid (148 SMs x 3 resident blocks), float2 per
// thread (lowest-register best-measured config), fused M in 32 regs, 2-deep
// software prefetch pipeline running continuously across the whole row loop.

#define QD 512
#define NBT (4 * 4096)       // 16384 rows
#define THREADS 256
#define NBLK 444             // 148 * 3 resident

__device__ __forceinline__ float2 f2_fma(float2 a, float2 b, float2 c) {
    return make_float2(fmaf(a.x, b.x, c.x), fmaf(a.y, b.y, c.y));
}
__device__ __forceinline__ float2 f2_mul(float2 a, float2 b) {
    return make_float2(a.x * b.x, a.y * b.y);
}

__global__ void __launch_bounds__(THREADS)
evolve_persist_kernel(const float* __restrict__ x,
                      const float* __restrict__ ql,
                      const float* __restrict__ qr,
                      const float* __restrict__ gate,
                      float* __restrict__ out) {
    const int d2 = threadIdx.x * 2;        // feature pair
    const int bid = blockIdx.x;

    // ---- Build fused 4x4 matrices for 2 features (elementwise float2) ----
    float2 lv[4], rv[4];
#pragma unroll
    for (int i = 0; i < 4; i++) {
        lv[i] = *reinterpret_cast<const float2*>(ql + i * QD + d2);
        rv[i] = *reinterpret_cast<const float2*>(qr + i * QD + d2);
    }
    {   // normalize l
        float2 s = make_float2(1e-8f, 1e-8f);
#pragma unroll
        for (int i = 0; i < 4; i++) s = f2_fma(lv[i], lv[i], s);
        float2 inv = make_float2(rsqrtf(s.x), rsqrtf(s.y));
#pragma unroll
        for (int i = 0; i < 4; i++) lv[i] = f2_mul(lv[i], inv);
    }
    {   // normalize r + conjugate
        float2 s = make_float2(1e-8f, 1e-8f);
#pragma unroll
        for (int i = 0; i < 4; i++) s = f2_fma(rv[i], rv[i], s);
        float2 inv = make_float2(rsqrtf(s.x), rsqrtf(s.y));
        rv[0] = f2_mul(rv[0], inv);
        float2 ninv = make_float2(-inv.x, -inv.y);
#pragma unroll
        for (int i = 1; i < 4; i++) rv[i] = f2_mul(rv[i], ninv);
    }

    // Hamilton structure (constant-folded): L[r][k]=sL*l[p[r][k]], R[k][c]=sR*r[p[k][c]]
    const int   pP[4][4] = {{0,1,2,3},{1,0,3,2},{2,3,0,1},{3,2,1,0}};
    const float sL[4][4] = {{1,-1,-1,-1},{1,1,-1,1},{1,1,1,-1},{1,-1,1,1}};
    const float sR[4][4] = {{1,-1,-1,-1},{1,1,1,-1},{1,-1,1,1},{1,1,-1,1}};

    float2 g2 = *reinterpret_cast<const float2*>(gate + d2);

    float2 M[16];
#pragma unroll
    for (int r = 0; r < 4; r++) {
#pragma unroll
        for (int c = 0; c < 4; c++) {
            float2 acc = make_float2(0.f, 0.f);
#pragma unroll
            for (int k = 0; k < 4; k++) {
                float2 t = f2_mul(lv[pP[r][k]], rv[pP[k][c]]);
                if (sL[r][k] * sR[k][c] > 0.f) { acc.x += t.x; acc.y += t.y; }
                else                           { acc.x -= t.x; acc.y -= t.y; }
            }
            M[r * 4 + c] = f2_mul(acc, g2);
        }
    }

    // ---- Persistent block-strided row loop with continuous 2-deep prefetch ----
    // Row r for block bid at iteration i: r = bid + i*NBLK.
    const float* xp = x + d2;
    float* op = out + d2;

    float2 buf[2][4];
    {
        size_t r0 = (size_t)bid * 2048;
        size_t r1 = (size_t)(bid + NBLK) * 2048;
#pragma unroll
        for (int c = 0; c < 4; c++)
            buf[0][c] = __ldcs(reinterpret_cast<const float2*>(xp + r0 + c * QD));
        if (bid + NBLK < NBT) {
#pragma unroll
            for (int c = 0; c < 4; c++)
                buf[1][c] = __ldcs(reinterpret_cast<const float2*>(xp + r1 + c * QD));
        }
    }

    int par = 0;
    for (int row = bid; row < NBT; row += NBLK, par ^= 1) {
        float2 in[4];
#pragma unroll
        for (int c = 0; c < 4; c++) in[c] = buf[par][c];

        int pf = row + 2 * NBLK;
        if (pf < NBT) {
            size_t rp = (size_t)pf * 2048;
#pragma unroll
            for (int c = 0; c < 4; c++)
                buf[par][c] = __ldcs(reinterpret_cast<const float2*>(xp + rp + c * QD));
        }

        size_t ro = (size_t)row * 2048;
#pragma unroll
        for (int r = 0; r < 4; r++) {
            float2 a = f2_mul(M[r * 4 + 0], in[0]);
            a = f2_fma(M[r * 4 + 1], in[1], a);
            a = f2_fma(M[r * 4 + 2], in[2], a);
            a = f2_fma(M[r * 4 + 3], in[3], a);
            __stcs(reinterpret_cast<float2*>(op + ro + r * QD), a);
        }
    }
}

extern "C" void kernel_launch(void* const* d_in, const int* in_sizes, int n_in,
                              void* d_out, int out_size) {
    const float* x    = (const float*)d_in[0];
    const float* ql   = (const float*)d_in[1];
    const float* qr   = (const float*)d_in[2];
    const float* gate = (const float*)d_in[3];
    float* out = (float*)d_out;

    evolve_persist_kernel<<<NBLK, THREADS>>>(x, ql, qr, gate, out);
}